// round 1
// baseline (speedup 1.0000x reference)
#include <cuda_runtime.h>
#include <math.h>

#define B_  2
#define T_  2048
#define D_  2048
#define H_  16
#define G_  4
#define DK_ 128
#define MT  (B_*T_)          // 4096 rows
#define KVW (G_*DK_)         // 512

// Scratch (device globals: allocation-free rule)
__device__ float g_q[(size_t)MT * D_];    // [B*T][H*DK]
__device__ float g_k[(size_t)MT * KVW];   // [B*T][G*DK]
__device__ float g_v[(size_t)MT * KVW];
__device__ float g_y[(size_t)MT * D_];    // attention output, head-interleaved

// ---------------------------------------------------------------------------
// SGEMM: C[M,N] = A[M,K] @ B[K,N], all row-major fp32.
// BM=BN=128, BK=16, 256 threads, 8x8 per thread. M%128==0, N%128==0, K%16==0.
// ---------------------------------------------------------------------------
__global__ __launch_bounds__(256) void sgemm128(const float* __restrict__ A,
                                                const float* __restrict__ Bm,
                                                float* __restrict__ C,
                                                int M, int N, int K)
{
    __shared__ float As[16][128];   // As[k][m]
    __shared__ float Bs[16][128];   // Bs[k][n]
    const int tid = threadIdx.x;
    const int bx = blockIdx.x, by = blockIdx.y;
    const float* Ab = A + (size_t)(by * 128) * K;
    const float* Bb = Bm + bx * 128;
    const int tx = tid & 15, ty = tid >> 4;
    const int m0 = ty * 8, n0 = tx * 8;

    float acc[8][8];
#pragma unroll
    for (int i = 0; i < 8; i++)
#pragma unroll
        for (int j = 0; j < 8; j++) acc[i][j] = 0.f;

    for (int k0 = 0; k0 < K; k0 += 16) {
#pragma unroll
        for (int l = 0; l < 2; l++) {
            int idx = tid + l * 256;            // 0..511 float4 slots
            int r = idx >> 2, c4 = idx & 3;     // A tile 128x16
            float4 a = *(const float4*)(Ab + (size_t)r * K + k0 + c4 * 4);
            As[c4 * 4 + 0][r] = a.x;
            As[c4 * 4 + 1][r] = a.y;
            As[c4 * 4 + 2][r] = a.z;
            As[c4 * 4 + 3][r] = a.w;
            int rb = idx >> 5, cb = idx & 31;   // B tile 16x128
            *(float4*)&Bs[rb][cb * 4] =
                *(const float4*)(Bb + (size_t)(k0 + rb) * N + cb * 4);
        }
        __syncthreads();
#pragma unroll
        for (int k = 0; k < 16; k++) {
            float ra[8], rb[8];
            *(float4*)(ra)     = *(float4*)&As[k][m0];
            *(float4*)(ra + 4) = *(float4*)&As[k][m0 + 4];
            *(float4*)(rb)     = *(float4*)&Bs[k][n0];
            *(float4*)(rb + 4) = *(float4*)&Bs[k][n0 + 4];
#pragma unroll
            for (int i = 0; i < 8; i++)
#pragma unroll
                for (int j = 0; j < 8; j++)
                    acc[i][j] = fmaf(ra[i], rb[j], acc[i][j]);
        }
        __syncthreads();
    }

    float* Cb = C + (size_t)(by * 128 + m0) * N + bx * 128 + n0;
#pragma unroll
    for (int i = 0; i < 8; i++) {
        *(float4*)(Cb + (size_t)i * N) =
            make_float4(acc[i][0], acc[i][1], acc[i][2], acc[i][3]);
        *(float4*)(Cb + (size_t)i * N + 4) =
            make_float4(acc[i][4], acc[i][5], acc[i][6], acc[i][7]);
    }
}

// ---------------------------------------------------------------------------
// RoPE in-place on [B*T][nh*128]; pairs (i, i+64) within each head.
// ---------------------------------------------------------------------------
__global__ void rope_kernel(float* __restrict__ q, int nh)
{
    int idx = blockIdx.x * blockDim.x + threadIdx.x;
    int total = MT * nh * 64;
    if (idx >= total) return;
    int i   = idx & 63;
    int h   = (idx >> 6) % nh;
    int row = idx / (64 * nh);
    int t   = row & (T_ - 1);
    float inv = powf(10000.f, -(float)i * (1.f / 64.f));
    float ang = (float)t * inv;
    float s, c;
    sincosf(ang, &s, &c);
    float* base = q + (size_t)row * nh * DK_ + h * DK_;
    float x1 = base[i], x2 = base[i + 64];
    base[i]      = x1 * c - x2 * s;
    base[i + 64] = x2 * c + x1 * s;
}

// ---------------------------------------------------------------------------
// Flash attention (fp32). Block: 64 q rows of one (b,h); 256 threads.
// Key tiles of 64; online softmax; O in registers (4 rows x 8 cols / thread).
// Shared strides chosen for bank-conflict freedom (see analysis).
// ---------------------------------------------------------------------------
#define SQ  130   // Qs row stride
#define SK  130   // K-phase row stride in KV buffer
#define SV  132   // V-phase row stride (float4-aligned)
#define SS  66    // score row stride
#define ATT_SMEM_FLOATS (64*SQ + 64*SV + 64*SS + 3*64)

__global__ __launch_bounds__(256) void attn_kernel(const float* __restrict__ q,
                                                   const float* __restrict__ k,
                                                   const float* __restrict__ v,
                                                   float* __restrict__ y)
{
    extern __shared__ float sm[];
    float* Qs   = sm;                 // [64][SQ]
    float* KV   = sm + 64 * SQ;       // K tiles stride SK, V tiles stride SV
    float* Ss   = KV + 64 * SV;       // [64][SS]
    float* mrow = Ss + 64 * SS;       // [64]
    float* lrow = mrow + 64;          // [64]
    float* arow = lrow + 64;          // [64]

    const int tid = threadIdx.x;
    const int q0  = blockIdx.x * 64;
    const int h   = blockIdx.y;
    const int b   = blockIdx.z;
    const int g   = h >> 2;                     // H/G = 4
    const float scale = 0.08838834764831845f;   // 1/sqrt(128)

    // Load Q tile (64 x 128) into Qs (stride SQ, scalar stores)
    const float* qbase = q + ((size_t)(b * T_ + q0)) * D_ + h * DK_;
#pragma unroll
    for (int l = 0; l < 8; l++) {
        int idx = tid + l * 256;          // 2048 float4 slots
        int r = idx >> 5, c4 = idx & 31;
        float4 a = *(const float4*)(qbase + (size_t)r * D_ + c4 * 4);
        float* dst = Qs + r * SQ + c4 * 4;
        dst[0] = a.x; dst[1] = a.y; dst[2] = a.z; dst[3] = a.w;
    }
    if (tid < 64) { mrow[tid] = -INFINITY; lrow[tid] = 0.f; }

    const int tx = tid & 15, ty = tid >> 4;
    const int i0 = ty * 4;         // 4 query rows per thread
    const int c0 = tx * 8;         // 8 output cols per thread (PV phase)
    // S-phase columns: tx + 16*j (j=0..3)  -> conflict-free K reads

    float o[4][8];
#pragma unroll
    for (int i = 0; i < 4; i++)
#pragma unroll
        for (int j = 0; j < 8; j++) o[i][j] = 0.f;

    const int nt = q0 / 64 + 1;    // causal: tiles 0..q0/64
    const float* kbase = k + ((size_t)(b * T_)) * KVW + g * DK_;
    const float* vbase = v + ((size_t)(b * T_)) * KVW + g * DK_;

    for (int jt = 0; jt < nt; jt++) {
        const int j0 = jt * 64;
        __syncthreads();   // prev PV done with KV/Ss
        // ---- load K tile (stride SK) ----
#pragma unroll
        for (int l = 0; l < 8; l++) {
            int idx = tid + l * 256;
            int r = idx >> 5, c4 = idx & 31;
            float4 a = *(const float4*)(kbase + (size_t)(j0 + r) * KVW + c4 * 4);
            float* dst = KV + r * SK + c4 * 4;
            dst[0] = a.x; dst[1] = a.y; dst[2] = a.z; dst[3] = a.w;
        }
        __syncthreads();
        // ---- S = Q K^T (4x4 per thread, cols tx+16j) ----
        float acc[4][4];
#pragma unroll
        for (int i = 0; i < 4; i++)
#pragma unroll
            for (int j = 0; j < 4; j++) acc[i][j] = 0.f;
#pragma unroll 4
        for (int d = 0; d < 128; d++) {
            float qv[4], kv[4];
#pragma unroll
            for (int i = 0; i < 4; i++) qv[i] = Qs[(i0 + i) * SQ + d];
#pragma unroll
            for (int j = 0; j < 4; j++) kv[j] = KV[(tx + 16 * j) * SK + d];
#pragma unroll
            for (int i = 0; i < 4; i++)
#pragma unroll
                for (int j = 0; j < 4; j++)
                    acc[i][j] = fmaf(qv[i], kv[j], acc[i][j]);
        }
        const bool diag = (jt == nt - 1);
#pragma unroll
        for (int i = 0; i < 4; i++)
#pragma unroll
            for (int j = 0; j < 4; j++) {
                int jc = tx + 16 * j;
                float val = acc[i][j] * scale;
                if (diag && (j0 + jc > q0 + i0 + i)) val = -INFINITY;
                Ss[(i0 + i) * SS + jc] = val;
            }
        __syncthreads();
        // ---- load V tile (stride SV, float4) + online softmax in parallel ----
#pragma unroll
        for (int l = 0; l < 8; l++) {
            int idx = tid + l * 256;
            int r = idx >> 5, c4 = idx & 31;
            float4 a = *(const float4*)(vbase + (size_t)(j0 + r) * KVW + c4 * 4);
            *(float4*)(KV + r * SV + c4 * 4) = a;
        }
        if (tid < 64) {
            int r = tid;
            float* srow = Ss + r * SS;
            float mold = mrow[r];
            float mnew = mold;
#pragma unroll 8
            for (int j = 0; j < 64; j++) mnew = fmaxf(mnew, srow[j]);
            float alpha = __expf(mold - mnew);
            float sum = 0.f;
#pragma unroll 8
            for (int j = 0; j < 64; j++) {
                float p = __expf(srow[j] - mnew);
                srow[j] = p;
                sum += p;
            }
            lrow[r] = lrow[r] * alpha + sum;
            mrow[r] = mnew;
            arow[r] = alpha;
        }
        __syncthreads();
        // ---- O = O*alpha + P @ V ----
        float al[4];
#pragma unroll
        for (int i = 0; i < 4; i++) al[i] = arow[i0 + i];
#pragma unroll
        for (int i = 0; i < 4; i++)
#pragma unroll
            for (int j = 0; j < 8; j++) o[i][j] *= al[i];
        for (int kk = 0; kk < 64; kk++) {
            float p[4];
#pragma unroll
            for (int i = 0; i < 4; i++) p[i] = Ss[(i0 + i) * SS + kk];
            float4 v0 = *(float4*)(KV + kk * SV + c0);
            float4 v1 = *(float4*)(KV + kk * SV + c0 + 4);
            float vv[8] = { v0.x, v0.y, v0.z, v0.w, v1.x, v1.y, v1.z, v1.w };
#pragma unroll
            for (int i = 0; i < 4; i++)
#pragma unroll
                for (int j = 0; j < 8; j++)
                    o[i][j] = fmaf(p[i], vv[j], o[i][j]);
        }
    }

    // epilogue: divide by l, write y[b, t, h*128 + c]
    float* ybase = y + ((size_t)(b * T_ + q0)) * D_ + h * DK_;
#pragma unroll
    for (int i = 0; i < 4; i++) {
        float inv = 1.f / lrow[i0 + i];
        float4 r0 = make_float4(o[i][0] * inv, o[i][1] * inv, o[i][2] * inv, o[i][3] * inv);
        float4 r1 = make_float4(o[i][4] * inv, o[i][5] * inv, o[i][6] * inv, o[i][7] * inv);
        *(float4*)(ybase + (size_t)(i0 + i) * D_ + c0)     = r0;
        *(float4*)(ybase + (size_t)(i0 + i) * D_ + c0 + 4) = r1;
    }
}

// ---------------------------------------------------------------------------
extern "C" void kernel_launch(void* const* d_in, const int* in_sizes, int n_in,
                              void* d_out, int out_size)
{
    const float* x  = (const float*)d_in[0];
    const float* Wq = (const float*)d_in[1];
    const float* Wk = (const float*)d_in[2];
    const float* Wv = (const float*)d_in[3];
    const float* Wo = (const float*)d_in[4];
    float* out = (float*)d_out;

    float *q, *k, *v, *y;
    cudaGetSymbolAddress((void**)&q, g_q);
    cudaGetSymbolAddress((void**)&k, g_k);
    cudaGetSymbolAddress((void**)&v, g_v);
    cudaGetSymbolAddress((void**)&y, g_y);

    dim3 blk(256);
    // QKV projections
    sgemm128<<<dim3(D_ / 128, MT / 128), blk>>>(x, Wq, q, MT, D_, D_);
    sgemm128<<<dim3(KVW / 128, MT / 128), blk>>>(x, Wk, k, MT, KVW, D_);
    sgemm128<<<dim3(KVW / 128, MT / 128), blk>>>(x, Wv, v, MT, KVW, D_);
    // RoPE
    int nq = MT * H_ * 64, nk = MT * G_ * 64;
    rope_kernel<<<(nq + 255) / 256, 256>>>(q, H_);
    rope_kernel<<<(nk + 255) / 256, 256>>>(k, G_);
    // Flash attention
    const int smem = ATT_SMEM_FLOATS * (int)sizeof(float);  // ~84.7 KB
    cudaFuncSetAttribute(attn_kernel, cudaFuncAttributeMaxDynamicSharedMemorySize, smem);
    attn_kernel<<<dim3(T_ / 64, H_, B_), blk, smem>>>(q, k, v, y);
    // Output projection
    sgemm128<<<dim3(D_ / 128, MT / 128), blk>>>(y, Wo, out, MT, D_, D_);
}

// round 3
// speedup vs baseline: 1.7029x; 1.7029x over previous
#include <cuda_runtime.h>
#include <cuda_bf16.h>
#include <math.h>
#include <stdint.h>

#define B_  2
#define T_  2048
#define D_  2048
#define H_  16
#define G_  4
#define DK_ 128
#define MT  (B_*T_)          // 4096 rows
#define KVW (G_*DK_)         // 512

// ---------------------------------------------------------------------------
// Scratch (device globals: allocation-free rule)
// ---------------------------------------------------------------------------
__device__ float g_q[(size_t)MT * D_];
__device__ float g_k[(size_t)MT * KVW];
__device__ float g_v[(size_t)MT * KVW];
__device__ float g_y[(size_t)MT * D_];

__device__ __nv_bfloat16 g_xh[(size_t)MT * D_];
__device__ __nv_bfloat16 g_xl[(size_t)MT * D_];
__device__ __nv_bfloat16 g_yh[(size_t)MT * D_];
__device__ __nv_bfloat16 g_yl[(size_t)MT * D_];
// transposed weights [N][K] bf16
__device__ __nv_bfloat16 g_wqh[(size_t)D_ * D_];
__device__ __nv_bfloat16 g_wql[(size_t)D_ * D_];
__device__ __nv_bfloat16 g_wkh[(size_t)KVW * D_];
__device__ __nv_bfloat16 g_wkl[(size_t)KVW * D_];
__device__ __nv_bfloat16 g_wvh[(size_t)KVW * D_];
__device__ __nv_bfloat16 g_wvl[(size_t)KVW * D_];
__device__ __nv_bfloat16 g_woh[(size_t)D_ * D_];
__device__ __nv_bfloat16 g_wol[(size_t)D_ * D_];

// ---------------------------------------------------------------------------
// Portable PTX helpers (valid at compute_103, no 'a' features)
// ---------------------------------------------------------------------------
__device__ __forceinline__ uint32_t smem_u32(const void* p) {
    uint32_t a;
    asm("{ .reg .u64 t; cvta.to.shared.u64 t, %1; cvt.u32.u64 %0, t; }" : "=r"(a) : "l"(p));
    return a;
}
__device__ __forceinline__ void cp16(uint32_t dst, const void* src) {
    asm volatile("cp.async.cg.shared.global [%0], [%1], 16;" :: "r"(dst), "l"(src));
}
#define CP_COMMIT() asm volatile("cp.async.commit_group;" ::: "memory")
#define CP_WAIT1()  asm volatile("cp.async.wait_group 1;" ::: "memory")
#define CP_WAIT0()  asm volatile("cp.async.wait_group 0;" ::: "memory")

__device__ __forceinline__ void ldm_x4(uint32_t* r, uint32_t addr) {
    asm volatile("ldmatrix.sync.aligned.m8n8.x4.shared.b16 {%0,%1,%2,%3}, [%4];"
                 : "=r"(r[0]), "=r"(r[1]), "=r"(r[2]), "=r"(r[3]) : "r"(addr));
}
__device__ __forceinline__ void mma16816(float* d, const uint32_t* a,
                                         uint32_t b0, uint32_t b1) {
    asm volatile("mma.sync.aligned.m16n8k16.row.col.f32.bf16.bf16.f32 "
                 "{%0,%1,%2,%3}, {%4,%5,%6,%7}, {%8,%9}, {%0,%1,%2,%3};"
                 : "+f"(d[0]), "+f"(d[1]), "+f"(d[2]), "+f"(d[3])
                 : "r"(a[0]), "r"(a[1]), "r"(a[2]), "r"(a[3]), "r"(b0), "r"(b1));
}

// ---------------------------------------------------------------------------
// fp32 -> bf16 hi/lo split (elementwise)
// ---------------------------------------------------------------------------
__global__ void split_bf16(const float* __restrict__ in, __nv_bfloat16* __restrict__ hi,
                           __nv_bfloat16* __restrict__ lo, int n4)
{
    int i = blockIdx.x * blockDim.x + threadIdx.x;
    if (i >= n4) return;
    float4 v = ((const float4*)in)[i];
    __nv_bfloat16 h0 = __float2bfloat16(v.x), h1 = __float2bfloat16(v.y);
    __nv_bfloat16 h2 = __float2bfloat16(v.z), h3 = __float2bfloat16(v.w);
    __nv_bfloat16 l0 = __float2bfloat16(v.x - __bfloat162float(h0));
    __nv_bfloat16 l1 = __float2bfloat16(v.y - __bfloat162float(h1));
    __nv_bfloat16 l2 = __float2bfloat16(v.z - __bfloat162float(h2));
    __nv_bfloat16 l3 = __float2bfloat16(v.w - __bfloat162float(h3));
    ((__nv_bfloat162*)hi)[i * 2]     = __nv_bfloat162(h0, h1);
    ((__nv_bfloat162*)hi)[i * 2 + 1] = __nv_bfloat162(h2, h3);
    ((__nv_bfloat162*)lo)[i * 2]     = __nv_bfloat162(l0, l1);
    ((__nv_bfloat162*)lo)[i * 2 + 1] = __nv_bfloat162(l2, l3);
}

// ---------------------------------------------------------------------------
// W[K][N] fp32 -> Wt_hi/lo[N][K] bf16 (transpose + split)
// ---------------------------------------------------------------------------
__global__ void tsplit_bf16(const float* __restrict__ W, __nv_bfloat16* __restrict__ Th,
                            __nv_bfloat16* __restrict__ Tl, int K, int N)
{
    __shared__ float t[32][33];
    int n0 = blockIdx.x * 32, k0 = blockIdx.y * 32;
    int tx = threadIdx.x, ty = threadIdx.y;
#pragma unroll
    for (int i = 0; i < 4; i++)
        t[ty + i * 8][tx] = W[(size_t)(k0 + ty + i * 8) * N + n0 + tx];
    __syncthreads();
#pragma unroll
    for (int i = 0; i < 4; i++) {
        float v = t[tx][ty + i * 8];
        __nv_bfloat16 h = __float2bfloat16(v);
        __nv_bfloat16 l = __float2bfloat16(v - __bfloat162float(h));
        size_t o = (size_t)(n0 + ty + i * 8) * K + k0 + tx;
        Th[o] = h;
        Tl[o] = l;
    }
}

// ---------------------------------------------------------------------------
// HMMA GEMM: C[M,N] = (Ah+Al)[M,K] @ (Bh+Bl)[N,K]^T, 3-term bf16 split.
// CTA 128x128, BK=64, 256 threads (8 warps, 2x4), double-buffered cp.async.
// Smem tile: 128 rows x 128B (64 bf16), SW128 swizzle, conflict-free ldmatrix.
// ---------------------------------------------------------------------------
#define GT_TILE  16384u
#define GT_STAGE 65536u
#define GEMM_SMEM (2 * 65536 + 128)

__global__ __launch_bounds__(256) void gemm_hmma_x3(
    const __nv_bfloat16* __restrict__ Ah, const __nv_bfloat16* __restrict__ Al,
    const __nv_bfloat16* __restrict__ Bh, const __nv_bfloat16* __restrict__ Bl,
    float* __restrict__ C, int M, int N, int Kd)
{
    extern __shared__ __align__(128) char dsm[];
    uint32_t dbase = smem_u32(dsm);
    const uint32_t base = (dbase + 127u) & ~127u;

    const int tid  = threadIdx.x;
    const int lane = tid & 31;
    const int w    = tid >> 5;
    const int wm   = w & 1;            // 2 warps along M
    const int wn   = w >> 1;           // 4 warps along N
    const int m0   = blockIdx.y * 128, n0 = blockIdx.x * 128;

    const __nv_bfloat16* srcs[4] = { Ah, Al, Bh, Bl };
    const int rowb[4] = { m0, m0, n0, n0 };

    float d[4][4][4];
#pragma unroll
    for (int mi = 0; mi < 4; mi++)
#pragma unroll
        for (int ni = 0; ni < 4; ni++)
#pragma unroll
            for (int r = 0; r < 4; r++) d[mi][ni][r] = 0.f;

    const int NC = Kd / 64;

    // stage loader
    auto load_stage = [&](int buf, int k0) {
        uint32_t sb = base + (uint32_t)buf * GT_STAGE;
#pragma unroll
        for (int t = 0; t < 4; t++) {
            const __nv_bfloat16* gp = srcs[t] + (size_t)rowb[t] * Kd + k0;
#pragma unroll
            for (int i = 0; i < 4; i++) {
                int id = tid + i * 256;
                int r = id >> 3, cc = id & 7;
                uint32_t dst = sb + t * GT_TILE +
                               (uint32_t)(r * 128 + ((cc ^ (r & 7)) << 4));
                cp16(dst, gp + (size_t)r * Kd + cc * 8);
            }
        }
    };

    load_stage(0, 0);
    CP_COMMIT();

    for (int c = 0; c < NC; c++) {
        if (c + 1 < NC) {
            load_stage((c + 1) & 1, (c + 1) * 64);
            CP_COMMIT();
            CP_WAIT1();
        } else {
            CP_WAIT0();
        }
        __syncthreads();

        const uint32_t sb = base + (uint32_t)(c & 1) * GT_STAGE;

        // A lane address pieces
        const int arow = wm * 64 + (lane & 15);
        const int akc0 = (lane >> 4);            // +0/+1 k-chunk within kstep
        const int asw  = arow & 7;
        // B lane address pieces
        const int brow = wn * 32 + (lane & 7) + ((lane >> 4) & 1) * 8;
        const int bkc0 = ((lane >> 3) & 1);
        const int bsw  = brow & 7;

#pragma unroll
        for (int ks = 0; ks < 4; ks++) {
            uint32_t af[2][4][4];
            uint32_t bf[2][2][4];
            const int akc = ks * 2 + akc0;
            const uint32_t aoff = (uint32_t)(arow * 128 + ((akc ^ asw) << 4));
#pragma unroll
            for (int term = 0; term < 2; term++) {
                uint32_t tb = sb + (uint32_t)term * GT_TILE + aoff;
#pragma unroll
                for (int mi = 0; mi < 4; mi++)
                    ldm_x4(af[term][mi], tb + (uint32_t)mi * 2048);
            }
            const int bkc = ks * 2 + bkc0;
            const uint32_t boff = (uint32_t)(brow * 128 + ((bkc ^ bsw) << 4));
#pragma unroll
            for (int term = 0; term < 2; term++) {
                uint32_t tb = sb + 2 * GT_TILE + (uint32_t)term * GT_TILE + boff;
#pragma unroll
                for (int np = 0; np < 2; np++)
                    ldm_x4(bf[term][np], tb + (uint32_t)np * 2048);
            }
#pragma unroll
            for (int mi = 0; mi < 4; mi++) {
#pragma unroll
                for (int ni = 0; ni < 4; ni++) {
                    const int bi = ni >> 1, rs = (ni & 1) * 2;
                    mma16816(d[mi][ni], af[0][mi], bf[0][bi][rs], bf[0][bi][rs + 1]);
                    mma16816(d[mi][ni], af[0][mi], bf[1][bi][rs], bf[1][bi][rs + 1]);
                    mma16816(d[mi][ni], af[1][mi], bf[0][bi][rs], bf[0][bi][rs + 1]);
                }
            }
        }
        __syncthreads();
    }

    // epilogue
    const int mb = m0 + wm * 64;
    const int nb = n0 + wn * 32;
#pragma unroll
    for (int mi = 0; mi < 4; mi++) {
#pragma unroll
        for (int ni = 0; ni < 4; ni++) {
            int r0 = mb + mi * 16 + (lane >> 2);
            int cc = nb + ni * 8 + (lane & 3) * 2;
            *(float2*)&C[(size_t)r0 * N + cc] = make_float2(d[mi][ni][0], d[mi][ni][1]);
            *(float2*)&C[(size_t)(r0 + 8) * N + cc] = make_float2(d[mi][ni][2], d[mi][ni][3]);
        }
    }
}

// ---------------------------------------------------------------------------
// RoPE in-place on [B*T][nh*128]; pairs (i, i+64) within each head.
// ---------------------------------------------------------------------------
__global__ void rope_kernel(float* __restrict__ q, int nh)
{
    int idx = blockIdx.x * blockDim.x + threadIdx.x;
    int total = MT * nh * 64;
    if (idx >= total) return;
    int i   = idx & 63;
    int h   = (idx >> 6) % nh;
    int row = idx / (64 * nh);
    int t   = row & (T_ - 1);
    float inv = powf(10000.f, -(float)i * (1.f / 64.f));
    float ang = (float)t * inv;
    float s, c;
    sincosf(ang, &s, &c);
    float* base = q + (size_t)row * nh * DK_ + h * DK_;
    float x1 = base[i], x2 = base[i + 64];
    base[i]      = x1 * c - x2 * s;
    base[i + 64] = x2 * c + x1 * s;
}

// ---------------------------------------------------------------------------
// Flash attention (fp32), unchanged from round 1 (passing version).
// ---------------------------------------------------------------------------
#define SQ  130
#define SK  130
#define SV  132
#define SS  66
#define ATT_SMEM_FLOATS (64*SQ + 64*SV + 64*SS + 3*64)

__global__ __launch_bounds__(256) void attn_kernel(const float* __restrict__ q,
                                                   const float* __restrict__ k,
                                                   const float* __restrict__ v,
                                                   float* __restrict__ y)
{
    extern __shared__ float sm[];
    float* Qs   = sm;
    float* KV   = sm + 64 * SQ;
    float* Ss   = KV + 64 * SV;
    float* mrow = Ss + 64 * SS;
    float* lrow = mrow + 64;
    float* arow = lrow + 64;

    const int tid = threadIdx.x;
    const int q0  = blockIdx.x * 64;
    const int h   = blockIdx.y;
    const int b   = blockIdx.z;
    const int g   = h >> 2;
    const float scale = 0.08838834764831845f;

    const float* qbase = q + ((size_t)(b * T_ + q0)) * D_ + h * DK_;
#pragma unroll
    for (int l = 0; l < 8; l++) {
        int idx = tid + l * 256;
        int r = idx >> 5, c4 = idx & 31;
        float4 a = *(const float4*)(qbase + (size_t)r * D_ + c4 * 4);
        float* dst = Qs + r * SQ + c4 * 4;
        dst[0] = a.x; dst[1] = a.y; dst[2] = a.z; dst[3] = a.w;
    }
    if (tid < 64) { mrow[tid] = -INFINITY; lrow[tid] = 0.f; }

    const int tx = tid & 15, ty = tid >> 4;
    const int i0 = ty * 4;
    const int c0 = tx * 8;

    float o[4][8];
#pragma unroll
    for (int i = 0; i < 4; i++)
#pragma unroll
        for (int j = 0; j < 8; j++) o[i][j] = 0.f;

    const int nt = q0 / 64 + 1;
    const float* kbase = k + ((size_t)(b * T_)) * KVW + g * DK_;
    const float* vbase = v + ((size_t)(b * T_)) * KVW + g * DK_;

    for (int jt = 0; jt < nt; jt++) {
        const int j0 = jt * 64;
        __syncthreads();
#pragma unroll
        for (int l = 0; l < 8; l++) {
            int idx = tid + l * 256;
            int r = idx >> 5, c4 = idx & 31;
            float4 a = *(const float4*)(kbase + (size_t)(j0 + r) * KVW + c4 * 4);
            float* dst = KV + r * SK + c4 * 4;
            dst[0] = a.x; dst[1] = a.y; dst[2] = a.z; dst[3] = a.w;
        }
        __syncthreads();
        float acc[4][4];
#pragma unroll
        for (int i = 0; i < 4; i++)
#pragma unroll
            for (int j = 0; j < 4; j++) acc[i][j] = 0.f;
#pragma unroll 4
        for (int dd = 0; dd < 128; dd++) {
            float qv[4], kv[4];
#pragma unroll
            for (int i = 0; i < 4; i++) qv[i] = Qs[(i0 + i) * SQ + dd];
#pragma unroll
            for (int j = 0; j < 4; j++) kv[j] = KV[(tx + 16 * j) * SK + dd];
#pragma unroll
            for (int i = 0; i < 4; i++)
#pragma unroll
                for (int j = 0; j < 4; j++)
                    acc[i][j] = fmaf(qv[i], kv[j], acc[i][j]);
        }
        const bool diag = (jt == nt - 1);
#pragma unroll
        for (int i = 0; i < 4; i++)
#pragma unroll
            for (int j = 0; j < 4; j++) {
                int jc = tx + 16 * j;
                float val = acc[i][j] * scale;
                if (diag && (j0 + jc > q0 + i0 + i)) val = -INFINITY;
                Ss[(i0 + i) * SS + jc] = val;
            }
        __syncthreads();
#pragma unroll
        for (int l = 0; l < 8; l++) {
            int idx = tid + l * 256;
            int r = idx >> 5, c4 = idx & 31;
            float4 a = *(const float4*)(vbase + (size_t)(j0 + r) * KVW + c4 * 4);
            *(float4*)(KV + r * SV + c4 * 4) = a;
        }
        if (tid < 64) {
            int r = tid;
            float* srow = Ss + r * SS;
            float mold = mrow[r];
            float mnew = mold;
#pragma unroll 8
            for (int j = 0; j < 64; j++) mnew = fmaxf(mnew, srow[j]);
            float alpha = __expf(mold - mnew);
            float sum = 0.f;
#pragma unroll 8
            for (int j = 0; j < 64; j++) {
                float p = __expf(srow[j] - mnew);
                srow[j] = p;
                sum += p;
            }
            lrow[r] = lrow[r] * alpha + sum;
            mrow[r] = mnew;
            arow[r] = alpha;
        }
        __syncthreads();
        float al[4];
#pragma unroll
        for (int i = 0; i < 4; i++) al[i] = arow[i0 + i];
#pragma unroll
        for (int i = 0; i < 4; i++)
#pragma unroll
            for (int j = 0; j < 8; j++) o[i][j] *= al[i];
        for (int kk = 0; kk < 64; kk++) {
            float p[4];
#pragma unroll
            for (int i = 0; i < 4; i++) p[i] = Ss[(i0 + i) * SS + kk];
            float4 v0 = *(float4*)(KV + kk * SV + c0);
            float4 v1 = *(float4*)(KV + kk * SV + c0 + 4);
            float vv[8] = { v0.x, v0.y, v0.z, v0.w, v1.x, v1.y, v1.z, v1.w };
#pragma unroll
            for (int i = 0; i < 4; i++)
#pragma unroll
                for (int j = 0; j < 8; j++)
                    o[i][j] = fmaf(p[i], vv[j], o[i][j]);
        }
    }

    float* ybase = y + ((size_t)(b * T_ + q0)) * D_ + h * DK_;
#pragma unroll
    for (int i = 0; i < 4; i++) {
        float inv = 1.f / lrow[i0 + i];
        float4 r0 = make_float4(o[i][0] * inv, o[i][1] * inv, o[i][2] * inv, o[i][3] * inv);
        float4 r1 = make_float4(o[i][4] * inv, o[i][5] * inv, o[i][6] * inv, o[i][7] * inv);
        *(float4*)(ybase + (size_t)(i0 + i) * D_ + c0)     = r0;
        *(float4*)(ybase + (size_t)(i0 + i) * D_ + c0 + 4) = r1;
    }
}

// ---------------------------------------------------------------------------
extern "C" void kernel_launch(void* const* d_in, const int* in_sizes, int n_in,
                              void* d_out, int out_size)
{
    const float* x  = (const float*)d_in[0];
    const float* Wq = (const float*)d_in[1];
    const float* Wk = (const float*)d_in[2];
    const float* Wv = (const float*)d_in[3];
    const float* Wo = (const float*)d_in[4];
    float* out = (float*)d_out;

    float *q, *k, *v, *y;
    cudaGetSymbolAddress((void**)&q, g_q);
    cudaGetSymbolAddress((void**)&k, g_k);
    cudaGetSymbolAddress((void**)&v, g_v);
    cudaGetSymbolAddress((void**)&y, g_y);
    __nv_bfloat16 *xh, *xl, *yh, *yl, *wqh, *wql, *wkh, *wkl, *wvh, *wvl, *woh, *wol;
    cudaGetSymbolAddress((void**)&xh, g_xh);   cudaGetSymbolAddress((void**)&xl, g_xl);
    cudaGetSymbolAddress((void**)&yh, g_yh);   cudaGetSymbolAddress((void**)&yl, g_yl);
    cudaGetSymbolAddress((void**)&wqh, g_wqh); cudaGetSymbolAddress((void**)&wql, g_wql);
    cudaGetSymbolAddress((void**)&wkh, g_wkh); cudaGetSymbolAddress((void**)&wkl, g_wkl);
    cudaGetSymbolAddress((void**)&wvh, g_wvh); cudaGetSymbolAddress((void**)&wvl, g_wvl);
    cudaGetSymbolAddress((void**)&woh, g_woh); cudaGetSymbolAddress((void**)&wol, g_wol);

    cudaFuncSetAttribute(gemm_hmma_x3, cudaFuncAttributeMaxDynamicSharedMemorySize, GEMM_SMEM);

    // Split inputs to bf16 hi/lo
    {
        int n4 = (MT * D_) / 4;
        split_bf16<<<(n4 + 255) / 256, 256>>>(x, xh, xl, n4);
    }
    tsplit_bf16<<<dim3(D_ / 32, D_ / 32), dim3(32, 8)>>>(Wq, wqh, wql, D_, D_);
    tsplit_bf16<<<dim3(KVW / 32, D_ / 32), dim3(32, 8)>>>(Wk, wkh, wkl, D_, KVW);
    tsplit_bf16<<<dim3(KVW / 32, D_ / 32), dim3(32, 8)>>>(Wv, wvh, wvl, D_, KVW);
    tsplit_bf16<<<dim3(D_ / 32, D_ / 32), dim3(32, 8)>>>(Wo, woh, wol, D_, D_);

    // QKV projections (HMMA bf16x3)
    gemm_hmma_x3<<<dim3(D_ / 128, MT / 128), 256, GEMM_SMEM>>>(xh, xl, wqh, wql, q, MT, D_, D_);
    gemm_hmma_x3<<<dim3(KVW / 128, MT / 128), 256, GEMM_SMEM>>>(xh, xl, wkh, wkl, k, MT, KVW, D_);
    gemm_hmma_x3<<<dim3(KVW / 128, MT / 128), 256, GEMM_SMEM>>>(xh, xl, wvh, wvl, v, MT, KVW, D_);

    // RoPE
    int nq = MT * H_ * 64, nk = MT * G_ * 64;
    rope_kernel<<<(nq + 255) / 256, 256>>>(q, H_);
    rope_kernel<<<(nk + 255) / 256, 256>>>(k, G_);

    // Flash attention (fp32)
    const int smem = ATT_SMEM_FLOATS * (int)sizeof(float);
    cudaFuncSetAttribute(attn_kernel, cudaFuncAttributeMaxDynamicSharedMemorySize, smem);
    attn_kernel<<<dim3(T_ / 64, H_, B_), 256, smem>>>(q, k, v, y);

    // Output projection (HMMA bf16x3)
    {
        int n4 = (MT * D_) / 4;
        split_bf16<<<(n4 + 255) / 256, 256>>>(y, yh, yl, n4);
    }
    gemm_hmma_x3<<<dim3(D_ / 128, MT / 128), 256, GEMM_SMEM>>>(yh, yl, woh, wol, out, MT, D_, D_);
}

// round 4
// speedup vs baseline: 3.1758x; 1.8649x over previous
#include <cuda_runtime.h>
#include <cuda_bf16.h>
#include <math.h>
#include <stdint.h>

#define B_  2
#define T_  2048
#define D_  2048
#define H_  16
#define G_  4
#define DK_ 128
#define MT  (B_*T_)          // 4096 rows
#define KVW (G_*DK_)         // 512

// ---------------------------------------------------------------------------
// Scratch (device globals: allocation-free rule)
// ---------------------------------------------------------------------------
__device__ float g_q[(size_t)MT * D_];
__device__ float g_k[(size_t)MT * KVW];
__device__ float g_v[(size_t)MT * KVW];

__device__ __nv_bfloat16 g_xh[(size_t)MT * D_];
__device__ __nv_bfloat16 g_xl[(size_t)MT * D_];
__device__ __nv_bfloat16 g_yh[(size_t)MT * D_];
__device__ __nv_bfloat16 g_yl[(size_t)MT * D_];
__device__ __nv_bfloat16 g_qh[(size_t)MT * D_];
__device__ __nv_bfloat16 g_ql[(size_t)MT * D_];
__device__ __nv_bfloat16 g_kh[(size_t)MT * KVW];
__device__ __nv_bfloat16 g_kl[(size_t)MT * KVW];
__device__ __nv_bfloat16 g_vh[(size_t)MT * KVW];
__device__ __nv_bfloat16 g_vl[(size_t)MT * KVW];
// transposed weights [N][K] bf16
__device__ __nv_bfloat16 g_wqh[(size_t)D_ * D_];
__device__ __nv_bfloat16 g_wql[(size_t)D_ * D_];
__device__ __nv_bfloat16 g_wkh[(size_t)KVW * D_];
__device__ __nv_bfloat16 g_wkl[(size_t)KVW * D_];
__device__ __nv_bfloat16 g_wvh[(size_t)KVW * D_];
__device__ __nv_bfloat16 g_wvl[(size_t)KVW * D_];
__device__ __nv_bfloat16 g_woh[(size_t)D_ * D_];
__device__ __nv_bfloat16 g_wol[(size_t)D_ * D_];

// ---------------------------------------------------------------------------
// Portable PTX helpers (valid at compute_103, no 'a' features)
// ---------------------------------------------------------------------------
__device__ __forceinline__ uint32_t smem_u32(const void* p) {
    uint32_t a;
    asm("{ .reg .u64 t; cvta.to.shared.u64 t, %1; cvt.u32.u64 %0, t; }" : "=r"(a) : "l"(p));
    return a;
}
__device__ __forceinline__ void cp16(uint32_t dst, const void* src) {
    asm volatile("cp.async.cg.shared.global [%0], [%1], 16;" :: "r"(dst), "l"(src));
}
#define CP_COMMIT() asm volatile("cp.async.commit_group;" ::: "memory")
#define CP_WAIT1()  asm volatile("cp.async.wait_group 1;" ::: "memory")
#define CP_WAIT0()  asm volatile("cp.async.wait_group 0;" ::: "memory")

__device__ __forceinline__ void ldm_x4(uint32_t* r, uint32_t addr) {
    asm volatile("ldmatrix.sync.aligned.m8n8.x4.shared.b16 {%0,%1,%2,%3}, [%4];"
                 : "=r"(r[0]), "=r"(r[1]), "=r"(r[2]), "=r"(r[3]) : "r"(addr));
}
__device__ __forceinline__ void ldm_x4t(uint32_t* r, uint32_t addr) {
    asm volatile("ldmatrix.sync.aligned.m8n8.x4.trans.shared.b16 {%0,%1,%2,%3}, [%4];"
                 : "=r"(r[0]), "=r"(r[1]), "=r"(r[2]), "=r"(r[3]) : "r"(addr));
}
__device__ __forceinline__ void mma16816(float* d, const uint32_t* a,
                                         uint32_t b0, uint32_t b1) {
    asm volatile("mma.sync.aligned.m16n8k16.row.col.f32.bf16.bf16.f32 "
                 "{%0,%1,%2,%3}, {%4,%5,%6,%7}, {%8,%9}, {%0,%1,%2,%3};"
                 : "+f"(d[0]), "+f"(d[1]), "+f"(d[2]), "+f"(d[3])
                 : "r"(a[0]), "r"(a[1]), "r"(a[2]), "r"(a[3]), "r"(b0), "r"(b1));
}
__device__ __forceinline__ uint32_t pack_bf16(float f0, float f1) {
    __nv_bfloat162 h = __floats2bfloat162_rn(f0, f1);
    return *(uint32_t*)&h;
}

// ---------------------------------------------------------------------------
// fp32 -> bf16 hi/lo split (elementwise)
// ---------------------------------------------------------------------------
__global__ void split_bf16(const float* __restrict__ in, __nv_bfloat16* __restrict__ hi,
                           __nv_bfloat16* __restrict__ lo, int n4)
{
    int i = blockIdx.x * blockDim.x + threadIdx.x;
    if (i >= n4) return;
    float4 v = ((const float4*)in)[i];
    __nv_bfloat16 h0 = __float2bfloat16(v.x), h1 = __float2bfloat16(v.y);
    __nv_bfloat16 h2 = __float2bfloat16(v.z), h3 = __float2bfloat16(v.w);
    __nv_bfloat16 l0 = __float2bfloat16(v.x - __bfloat162float(h0));
    __nv_bfloat16 l1 = __float2bfloat16(v.y - __bfloat162float(h1));
    __nv_bfloat16 l2 = __float2bfloat16(v.z - __bfloat162float(h2));
    __nv_bfloat16 l3 = __float2bfloat16(v.w - __bfloat162float(h3));
    ((__nv_bfloat162*)hi)[i * 2]     = __nv_bfloat162(h0, h1);
    ((__nv_bfloat162*)hi)[i * 2 + 1] = __nv_bfloat162(h2, h3);
    ((__nv_bfloat162*)lo)[i * 2]     = __nv_bfloat162(l0, l1);
    ((__nv_bfloat162*)lo)[i * 2 + 1] = __nv_bfloat162(l2, l3);
}

// ---------------------------------------------------------------------------
// RoPE + split: read fp32 [B*T][nh*128], rotate pairs (i, i+64), write hi/lo.
// ---------------------------------------------------------------------------
__global__ void rope_split(const float* __restrict__ src, __nv_bfloat16* __restrict__ hi,
                           __nv_bfloat16* __restrict__ lo, int nh)
{
    int idx = blockIdx.x * blockDim.x + threadIdx.x;
    int total = MT * nh * 64;
    if (idx >= total) return;
    int i   = idx & 63;
    int h   = (idx >> 6) % nh;
    int row = idx / (64 * nh);
    int t   = row & (T_ - 1);
    float inv = powf(10000.f, -(float)i * (1.f / 64.f));
    float ang = (float)t * inv;
    float s, c;
    sincosf(ang, &s, &c);
    size_t base = (size_t)row * nh * DK_ + h * DK_;
    float x1 = src[base + i], x2 = src[base + i + 64];
    float r1 = x1 * c - x2 * s;
    float r2 = x2 * c + x1 * s;
    __nv_bfloat16 h1 = __float2bfloat16(r1);
    __nv_bfloat16 h2 = __float2bfloat16(r2);
    hi[base + i]      = h1;
    hi[base + i + 64] = h2;
    lo[base + i]      = __float2bfloat16(r1 - __bfloat162float(h1));
    lo[base + i + 64] = __float2bfloat16(r2 - __bfloat162float(h2));
}

// ---------------------------------------------------------------------------
// W[K][N] fp32 -> Wt_hi/lo[N][K] bf16 (transpose + split)
// ---------------------------------------------------------------------------
__global__ void tsplit_bf16(const float* __restrict__ W, __nv_bfloat16* __restrict__ Th,
                            __nv_bfloat16* __restrict__ Tl, int K, int N)
{
    __shared__ float t[32][33];
    int n0 = blockIdx.x * 32, k0 = blockIdx.y * 32;
    int tx = threadIdx.x, ty = threadIdx.y;
#pragma unroll
    for (int i = 0; i < 4; i++)
        t[ty + i * 8][tx] = W[(size_t)(k0 + ty + i * 8) * N + n0 + tx];
    __syncthreads();
#pragma unroll
    for (int i = 0; i < 4; i++) {
        float v = t[tx][ty + i * 8];
        __nv_bfloat16 h = __float2bfloat16(v);
        __nv_bfloat16 l = __float2bfloat16(v - __bfloat162float(h));
        size_t o = (size_t)(n0 + ty + i * 8) * K + k0 + tx;
        Th[o] = h;
        Tl[o] = l;
    }
}

// ---------------------------------------------------------------------------
// HMMA GEMM (unchanged from R3, verified): C = (Ah+Al)(Bh+Bl)^T, 3-term.
// ---------------------------------------------------------------------------
#define GT_TILE  16384u
#define GT_STAGE 65536u
#define GEMM_SMEM (2 * 65536 + 128)

__global__ __launch_bounds__(256) void gemm_hmma_x3(
    const __nv_bfloat16* __restrict__ Ah, const __nv_bfloat16* __restrict__ Al,
    const __nv_bfloat16* __restrict__ Bh, const __nv_bfloat16* __restrict__ Bl,
    float* __restrict__ C, int M, int N, int Kd)
{
    extern __shared__ __align__(128) char dsm[];
    uint32_t dbase = smem_u32(dsm);
    const uint32_t base = (dbase + 127u) & ~127u;

    const int tid  = threadIdx.x;
    const int lane = tid & 31;
    const int w    = tid >> 5;
    const int wm   = w & 1;
    const int wn   = w >> 1;
    const int m0   = blockIdx.y * 128, n0 = blockIdx.x * 128;

    const __nv_bfloat16* srcs[4] = { Ah, Al, Bh, Bl };
    const int rowb[4] = { m0, m0, n0, n0 };

    float d[4][4][4];
#pragma unroll
    for (int mi = 0; mi < 4; mi++)
#pragma unroll
        for (int ni = 0; ni < 4; ni++)
#pragma unroll
            for (int r = 0; r < 4; r++) d[mi][ni][r] = 0.f;

    const int NC = Kd / 64;

    auto load_stage = [&](int buf, int k0) {
        uint32_t sb = base + (uint32_t)buf * GT_STAGE;
#pragma unroll
        for (int t = 0; t < 4; t++) {
            const __nv_bfloat16* gp = srcs[t] + (size_t)rowb[t] * Kd + k0;
#pragma unroll
            for (int i = 0; i < 4; i++) {
                int id = tid + i * 256;
                int r = id >> 3, cc = id & 7;
                uint32_t dst = sb + t * GT_TILE +
                               (uint32_t)(r * 128 + ((cc ^ (r & 7)) << 4));
                cp16(dst, gp + (size_t)r * Kd + cc * 8);
            }
        }
    };

    load_stage(0, 0);
    CP_COMMIT();

    for (int c = 0; c < NC; c++) {
        if (c + 1 < NC) {
            load_stage((c + 1) & 1, (c + 1) * 64);
            CP_COMMIT();
            CP_WAIT1();
        } else {
            CP_WAIT0();
        }
        __syncthreads();

        const uint32_t sb = base + (uint32_t)(c & 1) * GT_STAGE;

        const int arow = wm * 64 + (lane & 15);
        const int akc0 = (lane >> 4);
        const int asw  = arow & 7;
        const int brow = wn * 32 + (lane & 7) + ((lane >> 4) & 1) * 8;
        const int bkc0 = ((lane >> 3) & 1);
        const int bsw  = brow & 7;

#pragma unroll
        for (int ks = 0; ks < 4; ks++) {
            uint32_t af[2][4][4];
            uint32_t bf[2][2][4];
            const int akc = ks * 2 + akc0;
            const uint32_t aoff = (uint32_t)(arow * 128 + ((akc ^ asw) << 4));
#pragma unroll
            for (int term = 0; term < 2; term++) {
                uint32_t tb = sb + (uint32_t)term * GT_TILE + aoff;
#pragma unroll
                for (int mi = 0; mi < 4; mi++)
                    ldm_x4(af[term][mi], tb + (uint32_t)mi * 2048);
            }
            const int bkc = ks * 2 + bkc0;
            const uint32_t boff = (uint32_t)(brow * 128 + ((bkc ^ bsw) << 4));
#pragma unroll
            for (int term = 0; term < 2; term++) {
                uint32_t tb = sb + 2 * GT_TILE + (uint32_t)term * GT_TILE + boff;
#pragma unroll
                for (int np = 0; np < 2; np++)
                    ldm_x4(bf[term][np], tb + (uint32_t)np * 2048);
            }
#pragma unroll
            for (int mi = 0; mi < 4; mi++) {
#pragma unroll
                for (int ni = 0; ni < 4; ni++) {
                    const int bi = ni >> 1, rs = (ni & 1) * 2;
                    mma16816(d[mi][ni], af[0][mi], bf[0][bi][rs], bf[0][bi][rs + 1]);
                    mma16816(d[mi][ni], af[0][mi], bf[1][bi][rs], bf[1][bi][rs + 1]);
                    mma16816(d[mi][ni], af[1][mi], bf[0][bi][rs], bf[0][bi][rs + 1]);
                }
            }
        }
        __syncthreads();
    }

    const int mb = m0 + wm * 64;
    const int nb = n0 + wn * 32;
#pragma unroll
    for (int mi = 0; mi < 4; mi++) {
#pragma unroll
        for (int ni = 0; ni < 4; ni++) {
            int r0 = mb + mi * 16 + (lane >> 2);
            int cc = nb + ni * 8 + (lane & 3) * 2;
            *(float2*)&C[(size_t)r0 * N + cc] = make_float2(d[mi][ni][0], d[mi][ni][1]);
            *(float2*)&C[(size_t)(r0 + 8) * N + cc] = make_float2(d[mi][ni][2], d[mi][ni][3]);
        }
    }
}

// ---------------------------------------------------------------------------
// HMMA flash attention, bf16x3 split everywhere.
// CTA: 128 q rows x one (b,h). 8 warps, 16 rows each. K-tile = 64 keys.
// Smem rows are 256B (128 bf16), chunk-xor swizzle (chunk ^ (row&7)).
// Output written directly as bf16 hi/lo (input to the Wo GEMM).
// ---------------------------------------------------------------------------
#define AT_SMEM (65536 + 32768 + 32768)

__global__ __launch_bounds__(256) void attn_hmma(
    const __nv_bfloat16* __restrict__ qh, const __nv_bfloat16* __restrict__ ql,
    const __nv_bfloat16* __restrict__ kh, const __nv_bfloat16* __restrict__ kl,
    const __nv_bfloat16* __restrict__ vh, const __nv_bfloat16* __restrict__ vl,
    __nv_bfloat16* __restrict__ yh, __nv_bfloat16* __restrict__ yl)
{
    extern __shared__ __align__(128) char dsm[];
    const uint32_t sQ = smem_u32(dsm);          // 2 x 32768 (hi, lo), 128 rows x 256B
    const uint32_t sK = sQ + 65536;             // 2 x 16384, 64 rows x 256B
    const uint32_t sV = sK + 32768;             // 2 x 16384

    const int tid = threadIdx.x, lane = tid & 31, w = tid >> 5;
    const int q0 = blockIdx.x * 128;
    const int h  = blockIdx.y;
    const int b  = blockIdx.z;
    const int g  = h >> 2;
    const float scale = 0.08838834764831845f;

    // ---- load Q tile (hi, lo) ----
    const __nv_bfloat16* qsrc[2] = {
        qh + ((size_t)(b * T_ + q0)) * D_ + h * DK_,
        ql + ((size_t)(b * T_ + q0)) * D_ + h * DK_ };
#pragma unroll
    for (int term = 0; term < 2; term++)
#pragma unroll
        for (int it = 0; it < 8; it++) {
            int slot = tid + it * 256;            // 2048 slots: 128 rows x 16 chunks
            int r = slot >> 4, ch = slot & 15;
            uint32_t dst = sQ + term * 32768 + (uint32_t)(r * 256 + ((ch ^ (r & 7)) << 4));
            cp16(dst, qsrc[term] + (size_t)r * D_ + ch * 8);
        }
    CP_COMMIT();

    const __nv_bfloat16* ksrc[2] = {
        kh + ((size_t)(b * T_)) * KVW + g * DK_,
        kl + ((size_t)(b * T_)) * KVW + g * DK_ };
    const __nv_bfloat16* vsrc[2] = {
        vh + ((size_t)(b * T_)) * KVW + g * DK_,
        vl + ((size_t)(b * T_)) * KVW + g * DK_ };

    float o[16][4];
#pragma unroll
    for (int ni = 0; ni < 16; ni++)
#pragma unroll
        for (int r = 0; r < 4; r++) o[ni][r] = 0.f;
    float m_run[2] = { -INFINITY, -INFINITY };
    float l_run[2] = { 0.f, 0.f };

    const int nt = 2 * blockIdx.x + 2;   // causal: k-tiles 0 .. nt-1

    // lane decompositions (constant per thread)
    const int arow = w * 16 + (lane & 15);
    const int akc0 = lane >> 4;
    const int asw  = arow & 7;
    const int kbrow_l = (lane & 7) + ((lane >> 4) & 1) * 8;  // + 16*nc
    const int kbkc0   = (lane >> 3) & 1;
    const int vrow_l  = (lane & 7) + ((lane >> 3) & 1) * 8;  // + 16*kk
    const int vnc0    = lane >> 4;

    for (int jt = 0; jt < nt; jt++) {
        const int j0 = jt * 64;
        __syncthreads();   // previous iteration done with K/V smem
        // ---- load K, V tiles (hi, lo) ----
#pragma unroll
        for (int term = 0; term < 2; term++)
#pragma unroll
            for (int it = 0; it < 4; it++) {
                int slot = tid + it * 256;        // 1024 slots: 64 rows x 16 chunks
                int r = slot >> 4, ch = slot & 15;
                uint32_t so = (uint32_t)(r * 256 + ((ch ^ (r & 7)) << 4));
                cp16(sK + term * 16384 + so, ksrc[term] + (size_t)(j0 + r) * KVW + ch * 8);
                cp16(sV + term * 16384 + so, vsrc[term] + (size_t)(j0 + r) * KVW + ch * 8);
            }
        CP_COMMIT();
        CP_WAIT0();
        __syncthreads();

        // ---- S = Q K^T (3-term) ----
        float s[8][4];
#pragma unroll
        for (int ni = 0; ni < 8; ni++)
#pragma unroll
            for (int r = 0; r < 4; r++) s[ni][r] = 0.f;

#pragma unroll
        for (int ks = 0; ks < 8; ks++) {
            uint32_t aq[2][4];
            const int akc = ks * 2 + akc0;
            const uint32_t aoff = (uint32_t)(arow * 256 + ((akc ^ asw) << 4));
            ldm_x4(aq[0], sQ + aoff);
            ldm_x4(aq[1], sQ + 32768 + aoff);
            uint32_t bk[2][4][4];
            const int bkc = ks * 2 + kbkc0;
#pragma unroll
            for (int nc = 0; nc < 4; nc++) {
                const int br = nc * 16 + kbrow_l;
                const uint32_t boff = (uint32_t)(br * 256 + ((bkc ^ (br & 7)) << 4));
                ldm_x4(bk[0][nc], sK + boff);
                ldm_x4(bk[1][nc], sK + 16384 + boff);
            }
#pragma unroll
            for (int ni = 0; ni < 8; ni++) {
                const int grp = ni >> 1, rs = (ni & 1) * 2;
                mma16816(s[ni], aq[0], bk[0][grp][rs], bk[0][grp][rs + 1]);
                mma16816(s[ni], aq[0], bk[1][grp][rs], bk[1][grp][rs + 1]);
                mma16816(s[ni], aq[1], bk[0][grp][rs], bk[0][grp][rs + 1]);
            }
        }

        // ---- scale + causal mask ----
        const bool needmask = (jt >= nt - 2);
        const int rbase = q0 + w * 16 + (lane >> 2);
        const int cbase = j0 + (lane & 3) * 2;
#pragma unroll
        for (int ni = 0; ni < 8; ni++)
#pragma unroll
            for (int r = 0; r < 4; r++) {
                float val = s[ni][r] * scale;
                if (needmask) {
                    int row = rbase + (r >> 1) * 8;
                    int col = cbase + ni * 8 + (r & 1);
                    if (col > row) val = -INFINITY;
                }
                s[ni][r] = val;
            }

        // ---- online softmax (registers + quad shuffles) ----
        float alpha[2];
#pragma unroll
        for (int rr = 0; rr < 2; rr++) {
            float mx = -INFINITY;
#pragma unroll
            for (int ni = 0; ni < 8; ni++)
                mx = fmaxf(mx, fmaxf(s[ni][rr * 2], s[ni][rr * 2 + 1]));
            mx = fmaxf(mx, __shfl_xor_sync(0xffffffffu, mx, 1));
            mx = fmaxf(mx, __shfl_xor_sync(0xffffffffu, mx, 2));
            float m_new = fmaxf(m_run[rr], mx);
            alpha[rr] = __expf(m_run[rr] - m_new);
            float sum = 0.f;
#pragma unroll
            for (int ni = 0; ni < 8; ni++) {
                float p0 = __expf(s[ni][rr * 2]     - m_new);
                float p1 = __expf(s[ni][rr * 2 + 1] - m_new);
                s[ni][rr * 2]     = p0;
                s[ni][rr * 2 + 1] = p1;
                sum += p0 + p1;
            }
            sum += __shfl_xor_sync(0xffffffffu, sum, 1);
            sum += __shfl_xor_sync(0xffffffffu, sum, 2);
            l_run[rr] = l_run[rr] * alpha[rr] + sum;
            m_run[rr] = m_new;
        }
#pragma unroll
        for (int ni = 0; ni < 16; ni++) {
            o[ni][0] *= alpha[0]; o[ni][1] *= alpha[0];
            o[ni][2] *= alpha[1]; o[ni][3] *= alpha[1];
        }

        // ---- O += P V (3-term; P repacked from S fragments) ----
#pragma unroll
        for (int kk = 0; kk < 4; kk++) {
            uint32_t pa_h[4], pa_l[4];
#pragma unroll
            for (int half = 0; half < 2; half++) {     // S n-tiles 2kk, 2kk+1
                const float* sp = s[2 * kk + half];
#pragma unroll
                for (int rr = 0; rr < 2; rr++) {
                    float f0 = sp[rr * 2], f1 = sp[rr * 2 + 1];
                    __nv_bfloat16 h0 = __float2bfloat16(f0);
                    __nv_bfloat16 h1 = __float2bfloat16(f1);
                    uint32_t ph;
                    {
                        __nv_bfloat162 t2(h0, h1);
                        ph = *(uint32_t*)&t2;
                    }
                    uint32_t pl = pack_bf16(f0 - __bfloat162float(h0),
                                            f1 - __bfloat162float(h1));
                    pa_h[half * 2 + rr] = ph;
                    pa_l[half * 2 + rr] = pl;
                }
            }
#pragma unroll
            for (int nc = 0; nc < 8; nc++) {
                uint32_t bv[2][4];
                const int vr = kk * 16 + vrow_l;
                const int vch = nc * 2 + vnc0;
                const uint32_t voff = (uint32_t)(vr * 256 + ((vch ^ (vr & 7)) << 4));
                ldm_x4t(bv[0], sV + voff);
                ldm_x4t(bv[1], sV + 16384 + voff);
                mma16816(o[2 * nc],     pa_h, bv[0][0], bv[0][1]);
                mma16816(o[2 * nc],     pa_h, bv[1][0], bv[1][1]);
                mma16816(o[2 * nc],     pa_l, bv[0][0], bv[0][1]);
                mma16816(o[2 * nc + 1], pa_h, bv[0][2], bv[0][3]);
                mma16816(o[2 * nc + 1], pa_h, bv[1][2], bv[1][3]);
                mma16816(o[2 * nc + 1], pa_l, bv[0][2], bv[0][3]);
            }
        }
    }

    // ---- epilogue: O / l, write bf16 hi/lo ----
    const int rowg = b * T_ + q0 + w * 16 + (lane >> 2);
    const int colg = h * DK_ + (lane & 3) * 2;
#pragma unroll
    for (int rr = 0; rr < 2; rr++) {
        float inv = 1.f / l_run[rr];
        size_t rb = (size_t)(rowg + rr * 8) * D_ + colg;
#pragma unroll
        for (int ni = 0; ni < 16; ni++) {
            float f0 = o[ni][rr * 2] * inv;
            float f1 = o[ni][rr * 2 + 1] * inv;
            __nv_bfloat16 h0 = __float2bfloat16(f0);
            __nv_bfloat16 h1 = __float2bfloat16(f1);
            *(__nv_bfloat162*)&yh[rb + ni * 8] = __nv_bfloat162(h0, h1);
            *(__nv_bfloat162*)&yl[rb + ni * 8] =
                __nv_bfloat162(__float2bfloat16(f0 - __bfloat162float(h0)),
                               __float2bfloat16(f1 - __bfloat162float(h1)));
        }
    }
}

// ---------------------------------------------------------------------------
extern "C" void kernel_launch(void* const* d_in, const int* in_sizes, int n_in,
                              void* d_out, int out_size)
{
    const float* x  = (const float*)d_in[0];
    const float* Wq = (const float*)d_in[1];
    const float* Wk = (const float*)d_in[2];
    const float* Wv = (const float*)d_in[3];
    const float* Wo = (const float*)d_in[4];
    float* out = (float*)d_out;

    float *q, *k, *v;
    cudaGetSymbolAddress((void**)&q, g_q);
    cudaGetSymbolAddress((void**)&k, g_k);
    cudaGetSymbolAddress((void**)&v, g_v);
    __nv_bfloat16 *xh, *xl, *yh, *yl, *qh, *ql, *kvh, *kvl, *vvh, *vvl;
    __nv_bfloat16 *wqh, *wql, *wkh, *wkl, *wvh, *wvl, *woh, *wol;
    cudaGetSymbolAddress((void**)&xh, g_xh);   cudaGetSymbolAddress((void**)&xl, g_xl);
    cudaGetSymbolAddress((void**)&yh, g_yh);   cudaGetSymbolAddress((void**)&yl, g_yl);
    cudaGetSymbolAddress((void**)&qh, g_qh);   cudaGetSymbolAddress((void**)&ql, g_ql);
    cudaGetSymbolAddress((void**)&kvh, g_kh);  cudaGetSymbolAddress((void**)&kvl, g_kl);
    cudaGetSymbolAddress((void**)&vvh, g_vh);  cudaGetSymbolAddress((void**)&vvl, g_vl);
    cudaGetSymbolAddress((void**)&wqh, g_wqh); cudaGetSymbolAddress((void**)&wql, g_wql);
    cudaGetSymbolAddress((void**)&wkh, g_wkh); cudaGetSymbolAddress((void**)&wkl, g_wkl);
    cudaGetSymbolAddress((void**)&wvh, g_wvh); cudaGetSymbolAddress((void**)&wvl, g_wvl);
    cudaGetSymbolAddress((void**)&woh, g_woh); cudaGetSymbolAddress((void**)&wol, g_wol);

    cudaFuncSetAttribute(gemm_hmma_x3, cudaFuncAttributeMaxDynamicSharedMemorySize, GEMM_SMEM);
    cudaFuncSetAttribute(attn_hmma, cudaFuncAttributeMaxDynamicSharedMemorySize, AT_SMEM);

    // Split inputs to bf16 hi/lo
    {
        int n4 = (MT * D_) / 4;
        split_bf16<<<(n4 + 255) / 256, 256>>>(x, xh, xl, n4);
    }
    tsplit_bf16<<<dim3(D_ / 32, D_ / 32), dim3(32, 8)>>>(Wq, wqh, wql, D_, D_);
    tsplit_bf16<<<dim3(KVW / 32, D_ / 32), dim3(32, 8)>>>(Wk, wkh, wkl, D_, KVW);
    tsplit_bf16<<<dim3(KVW / 32, D_ / 32), dim3(32, 8)>>>(Wv, wvh, wvl, D_, KVW);
    tsplit_bf16<<<dim3(D_ / 32, D_ / 32), dim3(32, 8)>>>(Wo, woh, wol, D_, D_);

    // QKV projections (HMMA bf16x3), fp32 results
    gemm_hmma_x3<<<dim3(D_ / 128, MT / 128), 256, GEMM_SMEM>>>(xh, xl, wqh, wql, q, MT, D_, D_);
    gemm_hmma_x3<<<dim3(KVW / 128, MT / 128), 256, GEMM_SMEM>>>(xh, xl, wkh, wkl, k, MT, KVW, D_);
    gemm_hmma_x3<<<dim3(KVW / 128, MT / 128), 256, GEMM_SMEM>>>(xh, xl, wvh, wvl, v, MT, KVW, D_);

    // RoPE + split q/k; split v
    int nq = MT * H_ * 64, nk = MT * G_ * 64;
    rope_split<<<(nq + 255) / 256, 256>>>(q, qh, ql, H_);
    rope_split<<<(nk + 255) / 256, 256>>>(k, kvh, kvl, G_);
    {
        int n4 = (MT * KVW) / 4;
        split_bf16<<<(n4 + 255) / 256, 256>>>(v, vvh, vvl, n4);
    }

    // HMMA flash attention -> yh/yl (bf16 split)
    attn_hmma<<<dim3(T_ / 128, H_, B_), 256, AT_SMEM>>>(qh, ql, kvh, kvl, vvh, vvl, yh, yl);

    // Output projection (HMMA bf16x3)
    gemm_hmma_x3<<<dim3(D_ / 128, MT / 128), 256, GEMM_SMEM>>>(yh, yl, woh, wol, out, MT, D_, D_);
}

// round 5
// speedup vs baseline: 3.2954x; 1.0377x over previous
#include <cuda_runtime.h>
#include <cuda_bf16.h>
#include <math.h>
#include <stdint.h>

#define B_  2
#define T_  2048
#define D_  2048
#define H_  16
#define G_  4
#define DK_ 128
#define MT  (B_*T_)          // 4096 rows
#define KVW (G_*DK_)         // 512

// ---------------------------------------------------------------------------
// Scratch (device globals: allocation-free rule)
// ---------------------------------------------------------------------------
__device__ float g_q[(size_t)MT * D_];
__device__ float g_k[(size_t)MT * KVW];
__device__ float g_v[(size_t)MT * KVW];

__device__ __nv_bfloat16 g_xh[(size_t)MT * D_];
__device__ __nv_bfloat16 g_xl[(size_t)MT * D_];
__device__ __nv_bfloat16 g_yh[(size_t)MT * D_];
__device__ __nv_bfloat16 g_yl[(size_t)MT * D_];
__device__ __nv_bfloat16 g_qh[(size_t)MT * D_];
__device__ __nv_bfloat16 g_ql[(size_t)MT * D_];
__device__ __nv_bfloat16 g_kh[(size_t)MT * KVW];
__device__ __nv_bfloat16 g_kl[(size_t)MT * KVW];
__device__ __nv_bfloat16 g_vh[(size_t)MT * KVW];
__device__ __nv_bfloat16 g_vl[(size_t)MT * KVW];
// transposed weights [N][K] bf16
__device__ __nv_bfloat16 g_wqh[(size_t)D_ * D_];
__device__ __nv_bfloat16 g_wql[(size_t)D_ * D_];
__device__ __nv_bfloat16 g_wkh[(size_t)KVW * D_];
__device__ __nv_bfloat16 g_wkl[(size_t)KVW * D_];
__device__ __nv_bfloat16 g_wvh[(size_t)KVW * D_];
__device__ __nv_bfloat16 g_wvl[(size_t)KVW * D_];
__device__ __nv_bfloat16 g_woh[(size_t)D_ * D_];
__device__ __nv_bfloat16 g_wol[(size_t)D_ * D_];

// ---------------------------------------------------------------------------
// Portable PTX helpers (valid at compute_103, no 'a' features)
// ---------------------------------------------------------------------------
__device__ __forceinline__ uint32_t smem_u32(const void* p) {
    uint32_t a;
    asm("{ .reg .u64 t; cvta.to.shared.u64 t, %1; cvt.u32.u64 %0, t; }" : "=r"(a) : "l"(p));
    return a;
}
__device__ __forceinline__ void cp16(uint32_t dst, const void* src) {
    asm volatile("cp.async.cg.shared.global [%0], [%1], 16;" :: "r"(dst), "l"(src));
}
#define CP_COMMIT() asm volatile("cp.async.commit_group;" ::: "memory")
#define CP_WAIT1()  asm volatile("cp.async.wait_group 1;" ::: "memory")
#define CP_WAIT0()  asm volatile("cp.async.wait_group 0;" ::: "memory")

__device__ __forceinline__ void ldm_x4(uint32_t* r, uint32_t addr) {
    asm volatile("ldmatrix.sync.aligned.m8n8.x4.shared.b16 {%0,%1,%2,%3}, [%4];"
                 : "=r"(r[0]), "=r"(r[1]), "=r"(r[2]), "=r"(r[3]) : "r"(addr));
}
__device__ __forceinline__ void ldm_x4t(uint32_t* r, uint32_t addr) {
    asm volatile("ldmatrix.sync.aligned.m8n8.x4.trans.shared.b16 {%0,%1,%2,%3}, [%4];"
                 : "=r"(r[0]), "=r"(r[1]), "=r"(r[2]), "=r"(r[3]) : "r"(addr));
}
__device__ __forceinline__ void mma16816(float* d, const uint32_t* a,
                                         uint32_t b0, uint32_t b1) {
    asm volatile("mma.sync.aligned.m16n8k16.row.col.f32.bf16.bf16.f32 "
                 "{%0,%1,%2,%3}, {%4,%5,%6,%7}, {%8,%9}, {%0,%1,%2,%3};"
                 : "+f"(d[0]), "+f"(d[1]), "+f"(d[2]), "+f"(d[3])
                 : "r"(a[0]), "r"(a[1]), "r"(a[2]), "r"(a[3]), "r"(b0), "r"(b1));
}
__device__ __forceinline__ uint32_t pack_bf16(float f0, float f1) {
    __nv_bfloat162 h = __floats2bfloat162_rn(f0, f1);
    return *(uint32_t*)&h;
}

// ---------------------------------------------------------------------------
// fp32 -> bf16 hi/lo split (elementwise)
// ---------------------------------------------------------------------------
__global__ void split_bf16(const float* __restrict__ in, __nv_bfloat16* __restrict__ hi,
                           __nv_bfloat16* __restrict__ lo, int n4)
{
    int i = blockIdx.x * blockDim.x + threadIdx.x;
    if (i >= n4) return;
    float4 v = ((const float4*)in)[i];
    __nv_bfloat16 h0 = __float2bfloat16(v.x), h1 = __float2bfloat16(v.y);
    __nv_bfloat16 h2 = __float2bfloat16(v.z), h3 = __float2bfloat16(v.w);
    __nv_bfloat16 l0 = __float2bfloat16(v.x - __bfloat162float(h0));
    __nv_bfloat16 l1 = __float2bfloat16(v.y - __bfloat162float(h1));
    __nv_bfloat16 l2 = __float2bfloat16(v.z - __bfloat162float(h2));
    __nv_bfloat16 l3 = __float2bfloat16(v.w - __bfloat162float(h3));
    ((__nv_bfloat162*)hi)[i * 2]     = __nv_bfloat162(h0, h1);
    ((__nv_bfloat162*)hi)[i * 2 + 1] = __nv_bfloat162(h2, h3);
    ((__nv_bfloat162*)lo)[i * 2]     = __nv_bfloat162(l0, l1);
    ((__nv_bfloat162*)lo)[i * 2 + 1] = __nv_bfloat162(l2, l3);
}

// ---------------------------------------------------------------------------
// RoPE + split: read fp32 [B*T][nh*128], rotate pairs (i, i+64), write hi/lo.
// ---------------------------------------------------------------------------
__global__ void rope_split(const float* __restrict__ src, __nv_bfloat16* __restrict__ hi,
                           __nv_bfloat16* __restrict__ lo, int nh)
{
    int idx = blockIdx.x * blockDim.x + threadIdx.x;
    int total = MT * nh * 64;
    if (idx >= total) return;
    int i   = idx & 63;
    int h   = (idx >> 6) % nh;
    int row = idx / (64 * nh);
    int t   = row & (T_ - 1);
    float inv = powf(10000.f, -(float)i * (1.f / 64.f));
    float ang = (float)t * inv;
    float s, c;
    sincosf(ang, &s, &c);
    size_t base = (size_t)row * nh * DK_ + h * DK_;
    float x1 = src[base + i], x2 = src[base + i + 64];
    float r1 = x1 * c - x2 * s;
    float r2 = x2 * c + x1 * s;
    __nv_bfloat16 h1 = __float2bfloat16(r1);
    __nv_bfloat16 h2 = __float2bfloat16(r2);
    hi[base + i]      = h1;
    hi[base + i + 64] = h2;
    lo[base + i]      = __float2bfloat16(r1 - __bfloat162float(h1));
    lo[base + i + 64] = __float2bfloat16(r2 - __bfloat162float(h2));
}

// ---------------------------------------------------------------------------
// W[K][N] fp32 -> Wt_hi/lo[N][K] bf16 (transpose + split)
// ---------------------------------------------------------------------------
__global__ void tsplit_bf16(const float* __restrict__ W, __nv_bfloat16* __restrict__ Th,
                            __nv_bfloat16* __restrict__ Tl, int K, int N)
{
    __shared__ float t[32][33];
    int n0 = blockIdx.x * 32, k0 = blockIdx.y * 32;
    int tx = threadIdx.x, ty = threadIdx.y;
#pragma unroll
    for (int i = 0; i < 4; i++)
        t[ty + i * 8][tx] = W[(size_t)(k0 + ty + i * 8) * N + n0 + tx];
    __syncthreads();
#pragma unroll
    for (int i = 0; i < 4; i++) {
        float v = t[tx][ty + i * 8];
        __nv_bfloat16 h = __float2bfloat16(v);
        __nv_bfloat16 l = __float2bfloat16(v - __bfloat162float(h));
        size_t o = (size_t)(n0 + ty + i * 8) * K + k0 + tx;
        Th[o] = h;
        Tl[o] = l;
    }
}

// ---------------------------------------------------------------------------
// HMMA GEMM: C = (Ah+Al)(Bh+Bl)^T, 3-term. Term-major MMA ordering so no
// back-to-back MMAs share an accumulator (HMMA latency > issue rate).
// ---------------------------------------------------------------------------
#define GT_TILE  16384u
#define GT_STAGE 65536u
#define GEMM_SMEM (2 * 65536 + 128)

__global__ __launch_bounds__(256) void gemm_hmma_x3(
    const __nv_bfloat16* __restrict__ Ah, const __nv_bfloat16* __restrict__ Al,
    const __nv_bfloat16* __restrict__ Bh, const __nv_bfloat16* __restrict__ Bl,
    float* __restrict__ C, int M, int N, int Kd)
{
    extern __shared__ __align__(128) char dsm[];
    uint32_t dbase = smem_u32(dsm);
    const uint32_t base = (dbase + 127u) & ~127u;

    const int tid  = threadIdx.x;
    const int lane = tid & 31;
    const int w    = tid >> 5;
    const int wm   = w & 1;
    const int wn   = w >> 1;
    const int m0   = blockIdx.y * 128, n0 = blockIdx.x * 128;

    const __nv_bfloat16* srcs[4] = { Ah, Al, Bh, Bl };
    const int rowb[4] = { m0, m0, n0, n0 };

    float d[4][4][4];
#pragma unroll
    for (int mi = 0; mi < 4; mi++)
#pragma unroll
        for (int ni = 0; ni < 4; ni++)
#pragma unroll
            for (int r = 0; r < 4; r++) d[mi][ni][r] = 0.f;

    const int NC = Kd / 64;

    auto load_stage = [&](int buf, int k0) {
        uint32_t sb = base + (uint32_t)buf * GT_STAGE;
#pragma unroll
        for (int t = 0; t < 4; t++) {
            const __nv_bfloat16* gp = srcs[t] + (size_t)rowb[t] * Kd + k0;
#pragma unroll
            for (int i = 0; i < 4; i++) {
                int id = tid + i * 256;
                int r = id >> 3, cc = id & 7;
                uint32_t dst = sb + t * GT_TILE +
                               (uint32_t)(r * 128 + ((cc ^ (r & 7)) << 4));
                cp16(dst, gp + (size_t)r * Kd + cc * 8);
            }
        }
    };

    load_stage(0, 0);
    CP_COMMIT();

    for (int c = 0; c < NC; c++) {
        if (c + 1 < NC) {
            load_stage((c + 1) & 1, (c + 1) * 64);
            CP_COMMIT();
            CP_WAIT1();
        } else {
            CP_WAIT0();
        }
        __syncthreads();

        const uint32_t sb = base + (uint32_t)(c & 1) * GT_STAGE;

        const int arow = wm * 64 + (lane & 15);
        const int akc0 = (lane >> 4);
        const int asw  = arow & 7;
        const int brow = wn * 32 + (lane & 7) + ((lane >> 4) & 1) * 8;
        const int bkc0 = ((lane >> 3) & 1);
        const int bsw  = brow & 7;

#pragma unroll
        for (int ks = 0; ks < 4; ks++) {
            uint32_t af[2][4][4];
            uint32_t bf[2][2][4];
            const int akc = ks * 2 + akc0;
            const uint32_t aoff = (uint32_t)(arow * 128 + ((akc ^ asw) << 4));
#pragma unroll
            for (int term = 0; term < 2; term++) {
                uint32_t tb = sb + (uint32_t)term * GT_TILE + aoff;
#pragma unroll
                for (int mi = 0; mi < 4; mi++)
                    ldm_x4(af[term][mi], tb + (uint32_t)mi * 2048);
            }
            const int bkc = ks * 2 + bkc0;
            const uint32_t boff = (uint32_t)(brow * 128 + ((bkc ^ bsw) << 4));
#pragma unroll
            for (int term = 0; term < 2; term++) {
                uint32_t tb = sb + 2 * GT_TILE + (uint32_t)term * GT_TILE + boff;
#pragma unroll
                for (int np = 0; np < 2; np++)
                    ldm_x4(bf[term][np], tb + (uint32_t)np * 2048);
            }
            // term-major: 16 distinct accumulators between reuses
#pragma unroll
            for (int mi = 0; mi < 4; mi++)
#pragma unroll
                for (int ni = 0; ni < 4; ni++) {
                    const int bi = ni >> 1, rs = (ni & 1) * 2;
                    mma16816(d[mi][ni], af[0][mi], bf[0][bi][rs], bf[0][bi][rs + 1]);
                }
#pragma unroll
            for (int mi = 0; mi < 4; mi++)
#pragma unroll
                for (int ni = 0; ni < 4; ni++) {
                    const int bi = ni >> 1, rs = (ni & 1) * 2;
                    mma16816(d[mi][ni], af[0][mi], bf[1][bi][rs], bf[1][bi][rs + 1]);
                }
#pragma unroll
            for (int mi = 0; mi < 4; mi++)
#pragma unroll
                for (int ni = 0; ni < 4; ni++) {
                    const int bi = ni >> 1, rs = (ni & 1) * 2;
                    mma16816(d[mi][ni], af[1][mi], bf[0][bi][rs], bf[0][bi][rs + 1]);
                }
        }
        __syncthreads();
    }

    const int mb = m0 + wm * 64;
    const int nb = n0 + wn * 32;
#pragma unroll
    for (int mi = 0; mi < 4; mi++) {
#pragma unroll
        for (int ni = 0; ni < 4; ni++) {
            int r0 = mb + mi * 16 + (lane >> 2);
            int cc = nb + ni * 8 + (lane & 3) * 2;
            *(float2*)&C[(size_t)r0 * N + cc] = make_float2(d[mi][ni][0], d[mi][ni][1]);
            *(float2*)&C[(size_t)(r0 + 8) * N + cc] = make_float2(d[mi][ni][2], d[mi][ni][3]);
        }
    }
}

// ---------------------------------------------------------------------------
// HMMA flash attention, bf16x3, double-buffered K/V, reversed CTA order.
// Smem: Q 64KB + K 2stages x 32KB + V 2stages x 32KB = 192KB.
// ---------------------------------------------------------------------------
#define AT_SMEM (65536 + 65536 + 65536)

__global__ __launch_bounds__(256) void attn_hmma(
    const __nv_bfloat16* __restrict__ qh, const __nv_bfloat16* __restrict__ ql,
    const __nv_bfloat16* __restrict__ kh, const __nv_bfloat16* __restrict__ kl,
    const __nv_bfloat16* __restrict__ vh, const __nv_bfloat16* __restrict__ vl,
    __nv_bfloat16* __restrict__ yh, __nv_bfloat16* __restrict__ yl)
{
    extern __shared__ __align__(128) char dsm[];
    const uint32_t sQ = smem_u32(dsm);           // 2 x 32768 (hi, lo)
    const uint32_t sK = sQ + 65536;              // 2 stages x (hi 16K + lo 16K)
    const uint32_t sV = sK + 65536;

    const int tid = threadIdx.x, lane = tid & 31, w = tid >> 5;
    const int q0 = (gridDim.x - 1 - blockIdx.x) * 128;   // heavy CTAs first
    const int h  = blockIdx.y;
    const int b  = blockIdx.z;
    const int g  = h >> 2;
    const float scale = 0.08838834764831845f;

    // ---- load Q tile (hi, lo) ----
    const __nv_bfloat16* qsrc[2] = {
        qh + ((size_t)(b * T_ + q0)) * D_ + h * DK_,
        ql + ((size_t)(b * T_ + q0)) * D_ + h * DK_ };
#pragma unroll
    for (int term = 0; term < 2; term++)
#pragma unroll
        for (int it = 0; it < 8; it++) {
            int slot = tid + it * 256;
            int r = slot >> 4, ch = slot & 15;
            uint32_t dst = sQ + term * 32768 + (uint32_t)(r * 256 + ((ch ^ (r & 7)) << 4));
            cp16(dst, qsrc[term] + (size_t)r * D_ + ch * 8);
        }
    CP_COMMIT();

    const __nv_bfloat16* ksrc[2] = {
        kh + ((size_t)(b * T_)) * KVW + g * DK_,
        kl + ((size_t)(b * T_)) * KVW + g * DK_ };
    const __nv_bfloat16* vsrc[2] = {
        vh + ((size_t)(b * T_)) * KVW + g * DK_,
        vl + ((size_t)(b * T_)) * KVW + g * DK_ };

    auto load_kv = [&](int stage, int j0) {
        uint32_t kb = sK + (uint32_t)stage * 32768;
        uint32_t vb = sV + (uint32_t)stage * 32768;
#pragma unroll
        for (int term = 0; term < 2; term++)
#pragma unroll
            for (int it = 0; it < 4; it++) {
                int slot = tid + it * 256;
                int r = slot >> 4, ch = slot & 15;
                uint32_t so = (uint32_t)(r * 256 + ((ch ^ (r & 7)) << 4));
                cp16(kb + term * 16384 + so, ksrc[term] + (size_t)(j0 + r) * KVW + ch * 8);
                cp16(vb + term * 16384 + so, vsrc[term] + (size_t)(j0 + r) * KVW + ch * 8);
            }
    };

    float o[16][4];
#pragma unroll
    for (int ni = 0; ni < 16; ni++)
#pragma unroll
        for (int r = 0; r < 4; r++) o[ni][r] = 0.f;
    float m_run[2] = { -INFINITY, -INFINITY };
    float l_run[2] = { 0.f, 0.f };

    const int nt = q0 / 64 + 2;    // causal: k-tiles 0 .. nt-1

    const int arow = w * 16 + (lane & 15);
    const int akc0 = lane >> 4;
    const int asw  = arow & 7;
    const int kbrow_l = (lane & 7) + ((lane >> 4) & 1) * 8;
    const int kbkc0   = (lane >> 3) & 1;
    const int vrow_l  = (lane & 7) + ((lane >> 3) & 1) * 8;
    const int vnc0    = lane >> 4;

    load_kv(0, 0);
    CP_COMMIT();

    for (int jt = 0; jt < nt; jt++) {
        const int cur = jt & 1;
        if (jt > 0) __syncthreads();   // prev compute done with stage being reloaded
        if (jt + 1 < nt) {
            load_kv(1 - cur, (jt + 1) * 64);
            CP_COMMIT();
            CP_WAIT1();
        } else {
            CP_WAIT0();
        }
        __syncthreads();

        const uint32_t sKs = sK + (uint32_t)cur * 32768;
        const uint32_t sVs = sV + (uint32_t)cur * 32768;
        const int j0 = jt * 64;

        // ---- S = Q K^T (3-term, term-major) ----
        float s[8][4];
#pragma unroll
        for (int ni = 0; ni < 8; ni++)
#pragma unroll
            for (int r = 0; r < 4; r++) s[ni][r] = 0.f;

#pragma unroll
        for (int ks = 0; ks < 8; ks++) {
            uint32_t aq[2][4];
            const int akc = ks * 2 + akc0;
            const uint32_t aoff = (uint32_t)(arow * 256 + ((akc ^ asw) << 4));
            ldm_x4(aq[0], sQ + aoff);
            ldm_x4(aq[1], sQ + 32768 + aoff);
            uint32_t bk[2][4][4];
            const int bkc = ks * 2 + kbkc0;
#pragma unroll
            for (int nc = 0; nc < 4; nc++) {
                const int br = nc * 16 + kbrow_l;
                const uint32_t boff = (uint32_t)(br * 256 + ((bkc ^ (br & 7)) << 4));
                ldm_x4(bk[0][nc], sKs + boff);
                ldm_x4(bk[1][nc], sKs + 16384 + boff);
            }
#pragma unroll
            for (int ni = 0; ni < 8; ni++) {
                const int grp = ni >> 1, rs = (ni & 1) * 2;
                mma16816(s[ni], aq[0], bk[0][grp][rs], bk[0][grp][rs + 1]);
            }
#pragma unroll
            for (int ni = 0; ni < 8; ni++) {
                const int grp = ni >> 1, rs = (ni & 1) * 2;
                mma16816(s[ni], aq[0], bk[1][grp][rs], bk[1][grp][rs + 1]);
            }
#pragma unroll
            for (int ni = 0; ni < 8; ni++) {
                const int grp = ni >> 1, rs = (ni & 1) * 2;
                mma16816(s[ni], aq[1], bk[0][grp][rs], bk[0][grp][rs + 1]);
            }
        }

        // ---- scale + causal mask ----
        const bool needmask = (jt >= nt - 2);
        const int rbase = q0 + w * 16 + (lane >> 2);
        const int cbase = j0 + (lane & 3) * 2;
#pragma unroll
        for (int ni = 0; ni < 8; ni++)
#pragma unroll
            for (int r = 0; r < 4; r++) {
                float val = s[ni][r] * scale;
                if (needmask) {
                    int row = rbase + (r >> 1) * 8;
                    int col = cbase + ni * 8 + (r & 1);
                    if (col > row) val = -INFINITY;
                }
                s[ni][r] = val;
            }

        // ---- online softmax ----
        float alpha[2];
#pragma unroll
        for (int rr = 0; rr < 2; rr++) {
            float mx = -INFINITY;
#pragma unroll
            for (int ni = 0; ni < 8; ni++)
                mx = fmaxf(mx, fmaxf(s[ni][rr * 2], s[ni][rr * 2 + 1]));
            mx = fmaxf(mx, __shfl_xor_sync(0xffffffffu, mx, 1));
            mx = fmaxf(mx, __shfl_xor_sync(0xffffffffu, mx, 2));
            float m_new = fmaxf(m_run[rr], mx);
            alpha[rr] = __expf(m_run[rr] - m_new);
            float sum = 0.f;
#pragma unroll
            for (int ni = 0; ni < 8; ni++) {
                float p0 = __expf(s[ni][rr * 2]     - m_new);
                float p1 = __expf(s[ni][rr * 2 + 1] - m_new);
                s[ni][rr * 2]     = p0;
                s[ni][rr * 2 + 1] = p1;
                sum += p0 + p1;
            }
            sum += __shfl_xor_sync(0xffffffffu, sum, 1);
            sum += __shfl_xor_sync(0xffffffffu, sum, 2);
            l_run[rr] = l_run[rr] * alpha[rr] + sum;
            m_run[rr] = m_new;
        }
#pragma unroll
        for (int ni = 0; ni < 16; ni++) {
            o[ni][0] *= alpha[0]; o[ni][1] *= alpha[0];
            o[ni][2] *= alpha[1]; o[ni][3] *= alpha[1];
        }

        // ---- O += P V (3-term, nc-pair interleave) ----
#pragma unroll
        for (int kk = 0; kk < 4; kk++) {
            uint32_t pa_h[4], pa_l[4];
#pragma unroll
            for (int half = 0; half < 2; half++) {
                const float* sp = s[2 * kk + half];
#pragma unroll
                for (int rr = 0; rr < 2; rr++) {
                    float f0 = sp[rr * 2], f1 = sp[rr * 2 + 1];
                    __nv_bfloat16 h0 = __float2bfloat16(f0);
                    __nv_bfloat16 h1 = __float2bfloat16(f1);
                    __nv_bfloat162 t2(h0, h1);
                    pa_h[half * 2 + rr] = *(uint32_t*)&t2;
                    pa_l[half * 2 + rr] = pack_bf16(f0 - __bfloat162float(h0),
                                                    f1 - __bfloat162float(h1));
                }
            }
            const int vr = kk * 16 + vrow_l;
#pragma unroll
            for (int ncp = 0; ncp < 4; ncp++) {
                uint32_t bv[2][2][4];   // [term][nc2][frag]
#pragma unroll
                for (int nc2 = 0; nc2 < 2; nc2++) {
                    const int nc = ncp * 2 + nc2;
                    const int vch = nc * 2 + vnc0;
                    const uint32_t voff = (uint32_t)(vr * 256 + ((vch ^ (vr & 7)) << 4));
                    ldm_x4t(bv[0][nc2], sVs + voff);
                    ldm_x4t(bv[1][nc2], sVs + 16384 + voff);
                }
                // 3 term-groups of 4 MMAs, all 4 distinct accumulators
#pragma unroll
                for (int nc2 = 0; nc2 < 2; nc2++) {
                    const int nc = ncp * 2 + nc2;
                    mma16816(o[2 * nc],     pa_h, bv[0][nc2][0], bv[0][nc2][1]);
                    mma16816(o[2 * nc + 1], pa_h, bv[0][nc2][2], bv[0][nc2][3]);
                }
#pragma unroll
                for (int nc2 = 0; nc2 < 2; nc2++) {
                    const int nc = ncp * 2 + nc2;
                    mma16816(o[2 * nc],     pa_h, bv[1][nc2][0], bv[1][nc2][1]);
                    mma16816(o[2 * nc + 1], pa_h, bv[1][nc2][2], bv[1][nc2][3]);
                }
#pragma unroll
                for (int nc2 = 0; nc2 < 2; nc2++) {
                    const int nc = ncp * 2 + nc2;
                    mma16816(o[2 * nc],     pa_l, bv[0][nc2][0], bv[0][nc2][1]);
                    mma16816(o[2 * nc + 1], pa_l, bv[0][nc2][2], bv[0][nc2][3]);
                }
            }
        }
    }

    // ---- epilogue: O / l, write bf16 hi/lo ----
    const int rowg = b * T_ + q0 + w * 16 + (lane >> 2);
    const int colg = h * DK_ + (lane & 3) * 2;
#pragma unroll
    for (int rr = 0; rr < 2; rr++) {
        float inv = 1.f / l_run[rr];
        size_t rb = (size_t)(rowg + rr * 8) * D_ + colg;
#pragma unroll
        for (int ni = 0; ni < 16; ni++) {
            float f0 = o[ni][rr * 2] * inv;
            float f1 = o[ni][rr * 2 + 1] * inv;
            __nv_bfloat16 h0 = __float2bfloat16(f0);
            __nv_bfloat16 h1 = __float2bfloat16(f1);
            *(__nv_bfloat162*)&yh[rb + ni * 8] = __nv_bfloat162(h0, h1);
            *(__nv_bfloat162*)&yl[rb + ni * 8] =
                __nv_bfloat162(__float2bfloat16(f0 - __bfloat162float(h0)),
                               __float2bfloat16(f1 - __bfloat162float(h1)));
        }
    }
}

// ---------------------------------------------------------------------------
extern "C" void kernel_launch(void* const* d_in, const int* in_sizes, int n_in,
                              void* d_out, int out_size)
{
    const float* x  = (const float*)d_in[0];
    const float* Wq = (const float*)d_in[1];
    const float* Wk = (const float*)d_in[2];
    const float* Wv = (const float*)d_in[3];
    const float* Wo = (const float*)d_in[4];
    float* out = (float*)d_out;

    float *q, *k, *v;
    cudaGetSymbolAddress((void**)&q, g_q);
    cudaGetSymbolAddress((void**)&k, g_k);
    cudaGetSymbolAddress((void**)&v, g_v);
    __nv_bfloat16 *xh, *xl, *yh, *yl, *qh, *ql, *kvh, *kvl, *vvh, *vvl;
    __nv_bfloat16 *wqh, *wql, *wkh, *wkl, *wvh, *wvl, *woh, *wol;
    cudaGetSymbolAddress((void**)&xh, g_xh);   cudaGetSymbolAddress((void**)&xl, g_xl);
    cudaGetSymbolAddress((void**)&yh, g_yh);   cudaGetSymbolAddress((void**)&yl, g_yl);
    cudaGetSymbolAddress((void**)&qh, g_qh);   cudaGetSymbolAddress((void**)&ql, g_ql);
    cudaGetSymbolAddress((void**)&kvh, g_kh);  cudaGetSymbolAddress((void**)&kvl, g_kl);
    cudaGetSymbolAddress((void**)&vvh, g_vh);  cudaGetSymbolAddress((void**)&vvl, g_vl);
    cudaGetSymbolAddress((void**)&wqh, g_wqh); cudaGetSymbolAddress((void**)&wql, g_wql);
    cudaGetSymbolAddress((void**)&wkh, g_wkh); cudaGetSymbolAddress((void**)&wkl, g_wkl);
    cudaGetSymbolAddress((void**)&wvh, g_wvh); cudaGetSymbolAddress((void**)&wvl, g_wvl);
    cudaGetSymbolAddress((void**)&woh, g_woh); cudaGetSymbolAddress((void**)&wol, g_wol);

    cudaFuncSetAttribute(gemm_hmma_x3, cudaFuncAttributeMaxDynamicSharedMemorySize, GEMM_SMEM);
    cudaFuncSetAttribute(attn_hmma, cudaFuncAttributeMaxDynamicSharedMemorySize, AT_SMEM);

    // Split inputs to bf16 hi/lo
    {
        int n4 = (MT * D_) / 4;
        split_bf16<<<(n4 + 255) / 256, 256>>>(x, xh, xl, n4);
    }
    tsplit_bf16<<<dim3(D_ / 32, D_ / 32), dim3(32, 8)>>>(Wq, wqh, wql, D_, D_);
    tsplit_bf16<<<dim3(KVW / 32, D_ / 32), dim3(32, 8)>>>(Wk, wkh, wkl, D_, KVW);
    tsplit_bf16<<<dim3(KVW / 32, D_ / 32), dim3(32, 8)>>>(Wv, wvh, wvl, D_, KVW);
    tsplit_bf16<<<dim3(D_ / 32, D_ / 32), dim3(32, 8)>>>(Wo, woh, wol, D_, D_);

    // QKV projections (HMMA bf16x3), fp32 results
    gemm_hmma_x3<<<dim3(D_ / 128, MT / 128), 256, GEMM_SMEM>>>(xh, xl, wqh, wql, q, MT, D_, D_);
    gemm_hmma_x3<<<dim3(KVW / 128, MT / 128), 256, GEMM_SMEM>>>(xh, xl, wkh, wkl, k, MT, KVW, D_);
    gemm_hmma_x3<<<dim3(KVW / 128, MT / 128), 256, GEMM_SMEM>>>(xh, xl, wvh, wvl, v, MT, KVW, D_);

    // RoPE + split q/k; split v
    int nq = MT * H_ * 64, nk = MT * G_ * 64;
    rope_split<<<(nq + 255) / 256, 256>>>(q, qh, ql, H_);
    rope_split<<<(nk + 255) / 256, 256>>>(k, kvh, kvl, G_);
    {
        int n4 = (MT * KVW) / 4;
        split_bf16<<<(n4 + 255) / 256, 256>>>(v, vvh, vvl, n4);
    }

    // HMMA flash attention -> yh/yl (bf16 split)
    attn_hmma<<<dim3(T_ / 128, H_, B_), 256, AT_SMEM>>>(qh, ql, kvh, kvl, vvh, vvl, yh, yl);

    // Output projection (HMMA bf16x3)
    gemm_hmma_x3<<<dim3(D_ / 128, MT / 128), 256, GEMM_SMEM>>>(yh, yl, woh, wol, out, MT, D_, D_);
}